// round 15
// baseline (speedup 1.0000x reference)
#include <cuda_runtime.h>
#include <cuda_bf16.h>
#include <cuda_fp16.h>
#include <math.h>
#include <stdint.h>

// Problem constants
#define LAYERS 2
#define BATCH  2
#define SEQ    2048
#define DMODEL 768
#define NHEADS 12
#define KVHEADS 4
#define NREP   3
#define HEADD  64
#define FFDIM  3072
#define ROWS   (BATCH*SEQ)     // 4096
#define QKVW   1280            // 768 q + 256 k + 256 v

#define GEMM_SMEM (3 * 49152)  // 3 stages x 48KB (A 32KB + B 16KB)

// ---------------------------------------------------------------------------
// Scratch (allocation-free: __device__ globals)
// Attention side = bf16, FFN side = fp16.
// ---------------------------------------------------------------------------
__device__ __nv_bfloat16 g_hp16[ROWS * DMODEL];
__device__ __half        g_hpf[ROWS * DMODEL];
__device__ float         g_qkv[ROWS * QKVW];
__device__ __nv_bfloat16 g_attnp[ROWS * DMODEL];
__device__ float         g_x[ROWS * DMODEL];
__device__ __half        g_ffp[ROWS * FFDIM];
__device__ unsigned g_wqkvp[LAYERS * DMODEL * QKVW / 2];
__device__ unsigned g_wop[LAYERS * DMODEL * DMODEL / 2];
__device__ unsigned g_w01p[LAYERS * DMODEL * 2 * FFDIM / 2];
__device__ unsigned g_w2p[LAYERS * FFDIM * DMODEL / 2];
__device__ float    g_freqs[32];   // rope freqs (f64-accurate, set in pack_all)

// ---------------------------------------------------------------------------
// cp.async helpers
// ---------------------------------------------------------------------------
__device__ __forceinline__ uint32_t smem_u32(const void* p) {
    return (uint32_t)__cvta_generic_to_shared(p);
}
__device__ __forceinline__ void cp16(uint32_t dst, const void* src) {
    asm volatile("cp.async.cg.shared.global [%0], [%1], 16;" :: "r"(dst), "l"(src));
}
__device__ __forceinline__ void cp_commit() { asm volatile("cp.async.commit_group;"); }
__device__ __forceinline__ void cp_wait1()  { asm volatile("cp.async.wait_group 1;"); }

// ---------------------------------------------------------------------------
// 16-bit packing helpers + shared k16 fragment layouts
// ---------------------------------------------------------------------------
__device__ __forceinline__ unsigned pack_bf16(float lo, float hi) {
    __nv_bfloat162 t = __floats2bfloat162_rn(lo, hi);
    return *reinterpret_cast<unsigned*>(&t);
}
__device__ __forceinline__ unsigned pack_f16(float lo, float hi) {
    __half2 t = __floats2half2_rn(lo, hi);
    return *reinterpret_cast<unsigned*>(&t);
}

__device__ __forceinline__ size_t aperm_off16(int m, int k) {  // element offset
    return (size_t)(k >> 4) * 65536 + (size_t)(m >> 4) * 256
         + ((m & 7) * 4 + ((k >> 1) & 3)) * 8
         + (((m >> 3) & 1) + 2 * ((k >> 3) & 1)) * 2 + (k & 1);
}
__device__ __forceinline__ size_t aperm_woff16(int m, int k) { // word offset, k even
    return (size_t)(k >> 4) * 32768 + (size_t)(m >> 4) * 128
         + ((m & 7) * 4 + ((k >> 1) & 3)) * 4
         + ((m >> 3) & 1) + 2 * ((k >> 3) & 1);
}

template<bool FP16>
__device__ __forceinline__ void mma16(float* d, const unsigned* a, const unsigned* b);
template<>
__device__ __forceinline__ void mma16<false>(float* d, const unsigned* a, const unsigned* b) {
    asm volatile("mma.sync.aligned.m16n8k16.row.col.f32.bf16.bf16.f32 "
        "{%0,%1,%2,%3}, {%4,%5,%6,%7}, {%8,%9}, {%0,%1,%2,%3};"
        : "+f"(d[0]), "+f"(d[1]), "+f"(d[2]), "+f"(d[3])
        : "r"(a[0]), "r"(a[1]), "r"(a[2]), "r"(a[3]), "r"(b[0]), "r"(b[1]));
}
template<>
__device__ __forceinline__ void mma16<true>(float* d, const unsigned* a, const unsigned* b) {
    asm volatile("mma.sync.aligned.m16n8k16.row.col.f32.f16.f16.f32 "
        "{%0,%1,%2,%3}, {%4,%5,%6,%7}, {%8,%9}, {%0,%1,%2,%3};"
        : "+f"(d[0]), "+f"(d[1]), "+f"(d[2]), "+f"(d[3])
        : "r"(a[0]), "r"(a[1]), "r"(a[2]), "r"(a[3]), "r"(b[0]), "r"(b[1]));
}

// ---------------------------------------------------------------------------
// Merged weight packing (one launch, 4 segments) + rope freq table
// ---------------------------------------------------------------------------
#define QKV_WORDS   (LAYERS * DMODEL * QKVW / 2)
#define WO_WORDS    (LAYERS * DMODEL * DMODEL / 2)
#define W01_WORDS   (LAYERS * DMODEL * 2 * FFDIM / 2)
#define W2_WORDS    (LAYERS * FFDIM * DMODEL / 2)
#define QKV_BLKS    ((QKV_WORDS + 255) / 256)
#define WO_BLKS     ((WO_WORDS + 255) / 256)
#define W01_BLKS    ((W01_WORDS + 255) / 256)
#define W2_BLKS     ((W2_WORDS + 255) / 256)
#define PACK_BLKS   (QKV_BLKS + WO_BLKS + W01_BLKS + W2_BLKS)

__device__ __forceinline__ void pack_coords16(int dw, int N, int& kbase, int& n) {
    int j  = dw & 1;
    int ln = (dw >> 1) & 31;
    int blk = dw >> 6;
    int n8cnt = N >> 3;
    int k16 = blk / n8cnt, n8 = blk - k16 * n8cnt;
    n = n8 * 8 + (ln >> 2);
    kbase = k16 * 16 + j * 8 + (ln & 3) * 2;
}

__global__ void __launch_bounds__(256) pack_all(const float* __restrict__ Wq,
                                                const float* __restrict__ Wk,
                                                const float* __restrict__ Wv,
                                                const float* __restrict__ Wo,
                                                const float* __restrict__ w0,
                                                const float* __restrict__ w1,
                                                const float* __restrict__ w2,
                                                unsigned* __restrict__ wqkvp,
                                                unsigned* __restrict__ wop,
                                                unsigned* __restrict__ w01p,
                                                unsigned* __restrict__ w2p)
{
    int bid = blockIdx.x;
    if (bid == 0 && threadIdx.x < 32)
        g_freqs[threadIdx.x] = (float)exp(-9.210340371976184 * ((double)threadIdx.x / 32.0));

    if (bid < QKV_BLKS) {
        int p = bid * 256 + threadIdx.x;
        if (p >= QKV_WORDS) return;
        const int perL = DMODEL * QKVW / 2;
        int l = p / perL, dw = p - l * perL;
        int k, n; pack_coords16(dw, QKVW, k, n);
        float v0, v1;
        if (n < 768) {
            const float* s = Wq + ((size_t)l * DMODEL + k) * 768 + n;
            v0 = s[0]; v1 = s[768];
        } else if (n < 1024) {
            const float* s = Wk + ((size_t)l * DMODEL + k) * 256 + (n - 768);
            v0 = s[0]; v1 = s[256];
        } else {
            const float* s = Wv + ((size_t)l * DMODEL + k) * 256 + (n - 1024);
            v0 = s[0]; v1 = s[256];
        }
        wqkvp[(size_t)l * perL + dw] = pack_bf16(v0, v1);
    } else if (bid < QKV_BLKS + WO_BLKS) {
        int p = (bid - QKV_BLKS) * 256 + threadIdx.x;
        if (p >= WO_WORDS) return;
        const int perL = DMODEL * DMODEL / 2;
        int l = p / perL, dw = p - l * perL;
        int k, n; pack_coords16(dw, DMODEL, k, n);
        const float* s = Wo + ((size_t)l * DMODEL + k) * DMODEL + n;
        wop[(size_t)l * perL + dw] = pack_bf16(s[0], s[DMODEL]);
    } else if (bid < QKV_BLKS + WO_BLKS + W01_BLKS) {
        int p = (bid - QKV_BLKS - WO_BLKS) * 256 + threadIdx.x;
        if (p >= W01_WORDS) return;
        const int perL = DMODEL * 2 * FFDIM / 2;
        int l = p / perL, dw = p - l * perL;
        int k, n; pack_coords16(dw, 2 * FFDIM, k, n);
        int f = n >> 1;
        const float* s = ((n & 1) ? w1 : w0) + ((size_t)l * DMODEL + k) * FFDIM + f;
        w01p[(size_t)l * perL + dw] = pack_f16(s[0], s[FFDIM]);
    } else {
        int p = (bid - QKV_BLKS - WO_BLKS - W01_BLKS) * 256 + threadIdx.x;
        if (p >= W2_WORDS) return;
        const int perL = FFDIM * DMODEL / 2;
        int l = p / perL, dw = p - l * perL;
        int k, n; pack_coords16(dw, DMODEL, k, n);
        const float* s = w2 + ((size_t)l * FFDIM + k) * DMODEL + n;
        w2p[(size_t)l * perL + dw] = pack_f16(s[0], s[DMODEL]);
    }
}

// ---------------------------------------------------------------------------
// RMSNorm: PERM 0 = fp32 row-major, 1 = fp16 A-perm, 2 = bf16 A-perm
// ---------------------------------------------------------------------------
template<int PERM>
__global__ void __launch_bounds__(256) rmsnorm_k(const float* __restrict__ x,
                                                 const float* __restrict__ w,
                                                 void* __restrict__ yv)
{
    int row = blockIdx.x;
    const float* xr = x + (size_t)row * DMODEL;
    int t = threadIdx.x;
    float v0 = xr[t], v1 = xr[t + 256], v2 = xr[t + 512];
    float ss = v0*v0 + v1*v1 + v2*v2;
    #pragma unroll
    for (int off = 16; off > 0; off >>= 1)
        ss += __shfl_xor_sync(0xffffffffu, ss, off);
    __shared__ float red[8];
    if ((t & 31) == 0) red[t >> 5] = ss;
    __syncthreads();
    if (t < 32) {
        float s = (t < 8) ? red[t] : 0.f;
        #pragma unroll
        for (int off = 4; off > 0; off >>= 1)
            s += __shfl_xor_sync(0xffffffffu, s, off);
        if (t == 0) red[0] = s;
    }
    __syncthreads();
    float inv = 1.0f / sqrtf(red[0] * (1.0f / DMODEL) + 1e-6f);
    float o0 = v0 * inv * w[t];
    float o1 = v1 * inv * w[t + 256];
    float o2 = v2 * inv * w[t + 512];
    if (PERM == 1) {
        __half* y = (__half*)yv;
        y[aperm_off16(row, t)]       = __float2half_rn(o0);
        y[aperm_off16(row, t + 256)] = __float2half_rn(o1);
        y[aperm_off16(row, t + 512)] = __float2half_rn(o2);
    } else if (PERM == 2) {
        __nv_bfloat16* y = (__nv_bfloat16*)yv;
        y[aperm_off16(row, t)]       = __float2bfloat16(o0);
        y[aperm_off16(row, t + 256)] = __float2bfloat16(o1);
        y[aperm_off16(row, t + 512)] = __float2bfloat16(o2);
    } else {
        float* yr = (float*)yv + (size_t)row * DMODEL;
        yr[t] = o0; yr[t + 256] = o1; yr[t + 512] = o2;
    }
}

// ---------------------------------------------------------------------------
// 16-bit tensor-core GEMM, 256x128 CTA tile, 3-stage cp.async pipeline.
// K-tile = 64. Stage = 48KB (A 32KB + B 16KB); 144KB dynamic smem; 1 CTA/SM.
// 8 warps as 2x4; warp tile 128x32 (mt 0..7, nt 0..3).
// MODE 0: C = AB fp32 row-major
// MODE 1: C = AB + R fp32 row-major (R may alias C)
// MODE 2: interleaved (w0,w1) -> silu(c0)*c1, fp16 A-perm out (K'=N/2)
// MODE 3: C = AB with RoPE applied to cols < 1024 (QKV projection)
// ---------------------------------------------------------------------------
template<int MODE, bool FP16>
__global__ void __launch_bounds__(256, 1) tgemm16_k(const void* __restrict__ Ap_,
                                                    const unsigned* __restrict__ Bp,
                                                    void* __restrict__ C_,
                                                    const float* __restrict__ R,
                                                    int N, int K)
{
    extern __shared__ unsigned sm16[];  // 3 x 12288 words; stage: A[0,8192) B[8192,12288)

    int tid = threadIdx.x, lane = tid & 31, warp = tid >> 5;
    int wm = warp >> 2, wn = warp & 3;
    int m0 = blockIdx.y * 256, n0 = blockIdx.x * 128;

    float acc[8][4][4];
    #pragma unroll
    for (int a = 0; a < 8; a++)
        #pragma unroll
        for (int b = 0; b < 4; b++)
            #pragma unroll
            for (int c = 0; c < 4; c++) acc[a][b][c] = 0.f;

    const int n8cnt = N >> 3;
    const uint4* Ag = (const uint4*)Ap_ + (size_t)((m0 >> 4) + 2 * warp) * 32 + lane;
    const uint4* Bg = (const uint4*)Bp + (size_t)((n0 >> 3) + (tid >> 4)) * 16 + (tid & 15);

    uint32_t smBase = smem_u32(sm16);
    uint32_t aDst = smBase + (2 * warp * 32 + lane) * 16;                  // +st*49152 +p*8192 +e*512
    uint32_t bDst = smBase + 32768 + ((tid >> 4) * 16 + (tid & 15)) * 16;  // +st*49152 +p*4096

    const int ntiles = K >> 6;

    #pragma unroll
    for (int t = 0; t < 2; t++) {
        uint32_t sb = t * 49152;
        #pragma unroll
        for (int p = 0; p < 4; p++) {
            int q = 4 * t + p;
            cp16(aDst + sb + p * 8192,       Ag + (size_t)q * 8192);
            cp16(aDst + sb + p * 8192 + 512, Ag + (size_t)q * 8192 + 32);
            cp16(bDst + sb + p * 4096,       Bg + (size_t)q * n8cnt * 16);
        }
        cp_commit();
    }

    for (int kt = 0; kt < ntiles; kt++) {
        cp_wait1();
        __syncthreads();
        const unsigned* S = sm16 + (kt % 3) * 12288;

        #pragma unroll
        for (int ks = 0; ks < 4; ks++) {
            unsigned af[8][4], bf[4][2];
            #pragma unroll
            for (int mt = 0; mt < 8; mt++)
                *(uint4*)af[mt] = *(const uint4*)&S[ks * 2048 + (wm * 8 + mt) * 128 + lane * 4];
            #pragma unroll
            for (int nt = 0; nt < 4; nt++)
                *(uint2*)bf[nt] = *(const uint2*)&S[8192 + ks * 1024 + (wn * 4 + nt) * 64 + lane * 2];
            #pragma unroll
            for (int mt = 0; mt < 8; mt++)
                #pragma unroll
                for (int nt = 0; nt < 4; nt++)
                    mma16<FP16>(acc[mt][nt], af[mt], bf[nt]);
        }

        int kn = kt + 2;
        if (kn < ntiles) {
            uint32_t sb = (kn % 3) * 49152;
            #pragma unroll
            for (int p = 0; p < 4; p++) {
                int q = 4 * kn + p;
                cp16(aDst + sb + p * 8192,       Ag + (size_t)q * 8192);
                cp16(aDst + sb + p * 8192 + 512, Ag + (size_t)q * 8192 + 32);
                cp16(bDst + sb + p * 4096,       Bg + (size_t)q * n8cnt * 16);
            }
        }
        cp_commit();
    }

    int g = lane >> 2, tg = lane & 3;
    #pragma unroll
    for (int mt = 0; mt < 8; mt++) {
        int row = m0 + wm * 128 + mt * 16 + g;
        #pragma unroll
        for (int nt = 0; nt < 4; nt++) {
            float* c = acc[mt][nt];
            if (MODE == 2) {
                int f = (n0 >> 1) + wn * 16 + nt * 4 + tg;
                float s0 = c[0] / (1.0f + __expf(-c[0]));
                float s2 = c[2] / (1.0f + __expf(-c[2]));
                __half* Cb = (__half*)C_;
                Cb[aperm_off16(row,     f)] = __float2half_rn(s0 * c[1]);
                Cb[aperm_off16(row + 8, f)] = __float2half_rn(s2 * c[3]);
            } else {
                float* C = (float*)C_;
                int col = n0 + wn * 32 + nt * 8 + tg * 2;
                size_t i0 = (size_t)row * N + col;
                size_t i1 = i0 + (size_t)8 * N;
                float2 v0 = make_float2(c[0], c[1]);
                float2 v1 = make_float2(c[2], c[3]);
                if (MODE == 3 && col < 1024) {
                    int i = (col & 63) >> 1;
                    float freq = g_freqs[i];
                    float sn0, cs0, sn1, cs1;
                    sincosf((float)(row & (SEQ - 1)) * freq, &sn0, &cs0);
                    sincosf((float)((row + 8) & (SEQ - 1)) * freq, &sn1, &cs1);
                    v0 = make_float2(c[0] * cs0 - c[1] * sn0, c[0] * sn0 + c[1] * cs0);
                    v1 = make_float2(c[2] * cs1 - c[3] * sn1, c[2] * sn1 + c[3] * cs1);
                }
                if (MODE == 1) {
                    v0.x += R[i0]; v0.y += R[i0 + 1];
                    v1.x += R[i1]; v1.y += R[i1 + 1];
                }
                *(float2*)&C[i0] = v0;
                *(float2*)&C[i1] = v1;
            }
        }
    }
}

// ---------------------------------------------------------------------------
// bf16 tensor-core flash attention, BK=64. Output bf16 A-perm.
// 128 threads = 4 warps; warp owns 16 q-rows for all keys. 32KB static smem.
// ---------------------------------------------------------------------------
__global__ void __launch_bounds__(128) flash_kernel(const float* __restrict__ qkv,
                                                    __nv_bfloat16* __restrict__ op)
{
    __shared__ unsigned Qs[4][4][32][4];   // [d16][m16][lane][j]
    __shared__ unsigned Ks[4][8][32][2];   // [d16][key8][lane][j]
    __shared__ unsigned Vs[4][8][32][2];   // [key16][dim8][lane][j]
    __shared__ unsigned Ps[4][4][32][4];   // [key16][m16][lane][j]

    int qt = blockIdx.x, h = blockIdx.y, b = blockIdx.z;
    int kvh = h / NREP;
    int tid = threadIdx.x, lane = tid & 31, warp = tid >> 5;
    int g = lane >> 2, tg = lane & 3;
    int q0 = qt * 64;

    const float* qbase = qkv + (size_t)(b * SEQ + q0) * QKVW + h * HEADD;
    for (int w = tid; w < 2048; w += 128) {
        int j = w & 3, ln = (w >> 2) & 31, m16 = (w >> 7) & 3, d16 = w >> 9;
        int m = m16 * 16 + (j & 1) * 8 + (ln >> 2);
        int d = d16 * 16 + ((j >> 1) & 1) * 8 + (ln & 3) * 2;
        float2 qv = *(const float2*)(qbase + (size_t)m * QKVW + d);
        Qs[d16][m16][ln][j] = pack_bf16(qv.x, qv.y);
    }

    float mr0 = -INFINITY, mr1 = -INFINITY, l0 = 0.f, l1 = 0.f;
    float o_acc[8][4];
    #pragma unroll
    for (int nt = 0; nt < 8; nt++)
        #pragma unroll
        for (int c = 0; c < 4; c++) o_acc[nt][c] = 0.f;

    const float* kbase = qkv + (size_t)(b * SEQ) * QKVW + 768 + kvh * HEADD;
    const float* vbase = qkv + (size_t)(b * SEQ) * QKVW + 1024 + kvh * HEADD;

    int ntiles = qt + 1;
    for (int kt = 0; kt < ntiles; kt++) {
        __syncthreads();
        for (int w = tid; w < 2048; w += 128) {
            int j = w & 1, ln = (w >> 1) & 31;
            int blk = (w >> 6) & 7, grp = w >> 9;   // grp 0..3
            {   // K: [d16=grp][key8=blk]
                int key = blk * 8 + (ln >> 2);
                int d = grp * 16 + j * 8 + (ln & 3) * 2;
                float2 kv = *(const float2*)(kbase + (size_t)(kt * 64 + key) * QKVW + d);
                Ks[grp][blk][ln][j] = pack_bf16(kv.x, kv.y);
            }
            {   // V: [key16=grp][dim8=blk]
                int dim = blk * 8 + (ln >> 2);
                int key = grp * 16 + j * 8 + (ln & 3) * 2;
                float v0 = vbase[(size_t)(kt * 64 + key) * QKVW + dim];
                float v1 = vbase[(size_t)(kt * 64 + key + 1) * QKVW + dim];
                Vs[grp][blk][ln][j] = pack_bf16(v0, v1);
            }
        }
        __syncthreads();

        float s[8][4];
        #pragma unroll
        for (int nt = 0; nt < 8; nt++)
            #pragma unroll
            for (int c = 0; c < 4; c++) s[nt][c] = 0.f;

        #pragma unroll
        for (int ks = 0; ks < 4; ks++) {
            unsigned af[4];
            *(uint4*)af = *(const uint4*)&Qs[ks][warp][lane][0];
            #pragma unroll
            for (int nt = 0; nt < 8; nt++) {
                unsigned bf[2];
                *(uint2*)bf = *(const uint2*)&Ks[ks][nt][lane][0];
                mma16<false>(s[nt], af, bf);
            }
        }
        #pragma unroll
        for (int nt = 0; nt < 8; nt++)
            #pragma unroll
            for (int c = 0; c < 4; c++) s[nt][c] *= 0.125f;

        if (kt == qt) {
            int qg0 = q0 + warp * 16 + g;
            int qg1 = qg0 + 8;
            #pragma unroll
            for (int nt = 0; nt < 8; nt++) {
                int kg = kt * 64 + nt * 8 + tg * 2;
                if (kg > qg0)     s[nt][0] = -INFINITY;
                if (kg + 1 > qg0) s[nt][1] = -INFINITY;
                if (kg > qg1)     s[nt][2] = -INFINITY;
                if (kg + 1 > qg1) s[nt][3] = -INFINITY;
            }
        }

        float mx0 = -INFINITY, mx1 = -INFINITY;
        #pragma unroll
        for (int nt = 0; nt < 8; nt++) {
            mx0 = fmaxf(mx0, fmaxf(s[nt][0], s[nt][1]));
            mx1 = fmaxf(mx1, fmaxf(s[nt][2], s[nt][3]));
        }
        mx0 = fmaxf(mx0, __shfl_xor_sync(0xffffffffu, mx0, 1));
        mx0 = fmaxf(mx0, __shfl_xor_sync(0xffffffffu, mx0, 2));
        mx1 = fmaxf(mx1, __shfl_xor_sync(0xffffffffu, mx1, 1));
        mx1 = fmaxf(mx1, __shfl_xor_sync(0xffffffffu, mx1, 2));
        float mn0 = fmaxf(mr0, mx0), mn1 = fmaxf(mr1, mx1);
        float sum0 = 0.f, sum1 = 0.f;
        #pragma unroll
        for (int nt = 0; nt < 8; nt++) {
            s[nt][0] = __expf(s[nt][0] - mn0);
            s[nt][1] = __expf(s[nt][1] - mn0);
            s[nt][2] = __expf(s[nt][2] - mn1);
            s[nt][3] = __expf(s[nt][3] - mn1);
            sum0 += s[nt][0] + s[nt][1];
            sum1 += s[nt][2] + s[nt][3];
        }
        sum0 += __shfl_xor_sync(0xffffffffu, sum0, 1);
        sum0 += __shfl_xor_sync(0xffffffffu, sum0, 2);
        sum1 += __shfl_xor_sync(0xffffffffu, sum1, 1);
        sum1 += __shfl_xor_sync(0xffffffffu, sum1, 2);
        float a0 = __expf(mr0 - mn0), a1 = __expf(mr1 - mn1);
        l0 = l0 * a0 + sum0;  l1 = l1 * a1 + sum1;
        mr0 = mn0;  mr1 = mn1;
        #pragma unroll
        for (int nt = 0; nt < 8; nt++) {
            o_acc[nt][0] *= a0; o_acc[nt][1] *= a0;
            o_acc[nt][2] *= a1; o_acc[nt][3] *= a1;
        }

        #pragma unroll
        for (int nt = 0; nt < 8; nt++) {
            Ps[nt >> 1][warp][lane][2 * (nt & 1)]     = pack_bf16(s[nt][0], s[nt][1]);
            Ps[nt >> 1][warp][lane][2 * (nt & 1) + 1] = pack_bf16(s[nt][2], s[nt][3]);
        }
        __syncwarp();

        #pragma unroll
        for (int kks = 0; kks < 4; kks++) {
            unsigned af[4];
            *(uint4*)af = *(const uint4*)&Ps[kks][warp][lane][0];
            #pragma unroll
            for (int nt = 0; nt < 8; nt++) {
                unsigned bf[2];
                *(uint2*)bf = *(const uint2*)&Vs[kks][nt][lane][0];
                mma16<false>(o_acc[nt], af, bf);
            }
        }
        __syncwarp();
    }

    float inv0 = 1.0f / l0, inv1 = 1.0f / l1;
    int mrow = b * SEQ + q0 + warp * 16 + g;
    unsigned* opw = (unsigned*)op;
    #pragma unroll
    for (int nt = 0; nt < 8; nt++) {
        int col = h * HEADD + nt * 8 + tg * 2;
        opw[aperm_woff16(mrow,     col)] = pack_bf16(o_acc[nt][0] * inv0, o_acc[nt][1] * inv0);
        opw[aperm_woff16(mrow + 8, col)] = pack_bf16(o_acc[nt][2] * inv1, o_acc[nt][3] * inv1);
    }
}

// ---------------------------------------------------------------------------
// Launch sequence
// ---------------------------------------------------------------------------
extern "C" void kernel_launch(void* const* d_in, const int* in_sizes, int n_in,
                              void* d_out, int out_size)
{
    (void)in_sizes; (void)n_in; (void)out_size;
    const float* x_in = (const float*)d_in[0];
    const float* Wq   = (const float*)d_in[1];
    const float* Wk   = (const float*)d_in[2];
    const float* Wv   = (const float*)d_in[3];
    const float* Wo   = (const float*)d_in[4];
    const float* an_w = (const float*)d_in[5];
    const float* w0   = (const float*)d_in[6];
    const float* w1   = (const float*)d_in[7];
    const float* w2   = (const float*)d_in[8];
    const float* sn_w = (const float*)d_in[9];
    const float* on_w = (const float*)d_in[10];

    __nv_bfloat16 *hp16, *attnp;
    __half *hpf, *ffp;
    float *qkv, *x;
    unsigned *wqkvp, *wop, *w01p, *w2p;
    cudaGetSymbolAddress((void**)&hp16,  g_hp16);
    cudaGetSymbolAddress((void**)&hpf,   g_hpf);
    cudaGetSymbolAddress((void**)&qkv,   g_qkv);
    cudaGetSymbolAddress((void**)&attnp, g_attnp);
    cudaGetSymbolAddress((void**)&x,     g_x);
    cudaGetSymbolAddress((void**)&ffp,   g_ffp);
    cudaGetSymbolAddress((void**)&wqkvp, g_wqkvp);
    cudaGetSymbolAddress((void**)&wop,   g_wop);
    cudaGetSymbolAddress((void**)&w01p,  g_w01p);
    cudaGetSymbolAddress((void**)&w2p,   g_w2p);

    // allow 144KB dynamic smem (idempotent; not a stream op)
    cudaFuncSetAttribute(tgemm16_k<3,false>, cudaFuncAttributeMaxDynamicSharedMemorySize, GEMM_SMEM);
    cudaFuncSetAttribute(tgemm16_k<1,false>, cudaFuncAttributeMaxDynamicSharedMemorySize, GEMM_SMEM);
    cudaFuncSetAttribute(tgemm16_k<1,true>,  cudaFuncAttributeMaxDynamicSharedMemorySize, GEMM_SMEM);
    cudaFuncSetAttribute(tgemm16_k<2,true>,  cudaFuncAttributeMaxDynamicSharedMemorySize, GEMM_SMEM);

    pack_all<<<PACK_BLKS, 256>>>(Wq, Wk, Wv, Wo, w0, w1, w2, wqkvp, wop, w01p, w2p);

    const float* cur = x_in;
    for (int li = 0; li < LAYERS; li++) {
        // attention side (bf16)
        rmsnorm_k<2><<<ROWS, 256>>>(cur, an_w + (size_t)li * DMODEL, hp16);

        // fused QKV projection + RoPE
        tgemm16_k<3,false><<<dim3(QKVW / 128, ROWS / 256), 256, GEMM_SMEM>>>(
            hp16, wqkvp + (size_t)li * DMODEL * QKVW / 2, qkv, nullptr, QKVW, DMODEL);

        flash_kernel<<<dim3(SEQ / 64, NHEADS, BATCH), 128>>>(qkv, attnp);

        tgemm16_k<1,false><<<dim3(DMODEL / 128, ROWS / 256), 256, GEMM_SMEM>>>(
            attnp, wop + (size_t)li * DMODEL * DMODEL / 2, x, cur, DMODEL, DMODEL);

        // FFN side (fp16)
        rmsnorm_k<1><<<ROWS, 256>>>(x, sn_w + (size_t)li * DMODEL, hpf);

        tgemm16_k<2,true><<<dim3(2 * FFDIM / 128, ROWS / 256), 256, GEMM_SMEM>>>(
            hpf, w01p + (size_t)li * DMODEL * 2 * FFDIM / 2, ffp, nullptr, 2 * FFDIM, DMODEL);

        tgemm16_k<1,true><<<dim3(DMODEL / 128, ROWS / 256), 256, GEMM_SMEM>>>(
            ffp, w2p + (size_t)li * FFDIM * DMODEL / 2, x, x, DMODEL, FFDIM);
        cur = x;
    }

    rmsnorm_k<0><<<ROWS, 256>>>(x, on_w, (float*)d_out);
}

// round 17
// speedup vs baseline: 1.0881x; 1.0881x over previous
#include <cuda_runtime.h>
#include <cuda_bf16.h>
#include <cuda_fp16.h>
#include <math.h>
#include <stdint.h>

// Problem constants
#define LAYERS 2
#define BATCH  2
#define SEQ    2048
#define DMODEL 768
#define NHEADS 12
#define KVHEADS 4
#define NREP   3
#define HEADD  64
#define FFDIM  3072
#define ROWS   (BATCH*SEQ)     // 4096
#define QKVW   1280            // 768 q + 256 k + 256 v

#define GEMM_SMEM (3 * 32768)  // 3 stages x 32KB

// ---------------------------------------------------------------------------
// Scratch (allocation-free: __device__ globals)
// Attention side = bf16, FFN side = fp16 (same eps as tf32, 2x speed).
// ---------------------------------------------------------------------------
__device__ __nv_bfloat16 g_hp16[ROWS * DMODEL];
__device__ __half        g_hpf[ROWS * DMODEL];
__device__ float         g_qkv[ROWS * QKVW];
__device__ __nv_bfloat16 g_attnp[ROWS * DMODEL];
__device__ float         g_x[ROWS * DMODEL];
__device__ __half        g_ffp[ROWS * FFDIM];
__device__ unsigned g_wqkvp[LAYERS * DMODEL * QKVW / 2];
__device__ unsigned g_wop[LAYERS * DMODEL * DMODEL / 2];
__device__ unsigned g_w01p[LAYERS * DMODEL * 2 * FFDIM / 2];
__device__ unsigned g_w2p[LAYERS * FFDIM * DMODEL / 2];

// ---------------------------------------------------------------------------
// cp.async helpers
// ---------------------------------------------------------------------------
__device__ __forceinline__ uint32_t smem_u32(const void* p) {
    return (uint32_t)__cvta_generic_to_shared(p);
}
__device__ __forceinline__ void cp16(uint32_t dst, const void* src) {
    asm volatile("cp.async.cg.shared.global [%0], [%1], 16;" :: "r"(dst), "l"(src));
}
__device__ __forceinline__ void cp_commit() { asm volatile("cp.async.commit_group;"); }
__device__ __forceinline__ void cp_wait1()  { asm volatile("cp.async.wait_group 1;"); }

// ---------------------------------------------------------------------------
// 16-bit packing helpers + shared k16 fragment layouts
// ---------------------------------------------------------------------------
__device__ __forceinline__ unsigned pack_bf16(float lo, float hi) {
    __nv_bfloat162 t = __floats2bfloat162_rn(lo, hi);
    return *reinterpret_cast<unsigned*>(&t);
}
__device__ __forceinline__ unsigned pack_f16(float lo, float hi) {
    __half2 t = __floats2half2_rn(lo, hi);
    return *reinterpret_cast<unsigned*>(&t);
}

__device__ __forceinline__ size_t aperm_off16(int m, int k) {  // element offset
    return (size_t)(k >> 4) * 65536 + (size_t)(m >> 4) * 256
         + ((m & 7) * 4 + ((k >> 1) & 3)) * 8
         + (((m >> 3) & 1) + 2 * ((k >> 3) & 1)) * 2 + (k & 1);
}
__device__ __forceinline__ size_t aperm_woff16(int m, int k) { // word offset, k even
    return (size_t)(k >> 4) * 32768 + (size_t)(m >> 4) * 128
         + ((m & 7) * 4 + ((k >> 1) & 3)) * 4
         + ((m >> 3) & 1) + 2 * ((k >> 3) & 1);
}

template<bool FP16>
__device__ __forceinline__ void mma16(float* d, const unsigned* a, const unsigned* b);
template<>
__device__ __forceinline__ void mma16<false>(float* d, const unsigned* a, const unsigned* b) {
    asm volatile("mma.sync.aligned.m16n8k16.row.col.f32.bf16.bf16.f32 "
        "{%0,%1,%2,%3}, {%4,%5,%6,%7}, {%8,%9}, {%0,%1,%2,%3};"
        : "+f"(d[0]), "+f"(d[1]), "+f"(d[2]), "+f"(d[3])
        : "r"(a[0]), "r"(a[1]), "r"(a[2]), "r"(a[3]), "r"(b[0]), "r"(b[1]));
}
template<>
__device__ __forceinline__ void mma16<true>(float* d, const unsigned* a, const unsigned* b) {
    asm volatile("mma.sync.aligned.m16n8k16.row.col.f32.f16.f16.f32 "
        "{%0,%1,%2,%3}, {%4,%5,%6,%7}, {%8,%9}, {%0,%1,%2,%3};"
        : "+f"(d[0]), "+f"(d[1]), "+f"(d[2]), "+f"(d[3])
        : "r"(a[0]), "r"(a[1]), "r"(a[2]), "r"(a[3]), "r"(b[0]), "r"(b[1]));
}

// ---------------------------------------------------------------------------
// Merged weight packing (one launch, 4 segments, all k16 B layout)
// ---------------------------------------------------------------------------
#define QKV_WORDS   (LAYERS * DMODEL * QKVW / 2)
#define WO_WORDS    (LAYERS * DMODEL * DMODEL / 2)
#define W01_WORDS   (LAYERS * DMODEL * 2 * FFDIM / 2)
#define W2_WORDS    (LAYERS * FFDIM * DMODEL / 2)
#define QKV_BLKS    ((QKV_WORDS + 255) / 256)
#define WO_BLKS     ((WO_WORDS + 255) / 256)
#define W01_BLKS    ((W01_WORDS + 255) / 256)
#define W2_BLKS     ((W2_WORDS + 255) / 256)
#define PACK_BLKS   (QKV_BLKS + WO_BLKS + W01_BLKS + W2_BLKS)

__device__ __forceinline__ void pack_coords16(int dw, int N, int& kbase, int& n) {
    int j  = dw & 1;
    int ln = (dw >> 1) & 31;
    int blk = dw >> 6;
    int n8cnt = N >> 3;
    int k16 = blk / n8cnt, n8 = blk - k16 * n8cnt;
    n = n8 * 8 + (ln >> 2);
    kbase = k16 * 16 + j * 8 + (ln & 3) * 2;
}

__global__ void __launch_bounds__(256) pack_all(const float* __restrict__ Wq,
                                                const float* __restrict__ Wk,
                                                const float* __restrict__ Wv,
                                                const float* __restrict__ Wo,
                                                const float* __restrict__ w0,
                                                const float* __restrict__ w1,
                                                const float* __restrict__ w2,
                                                unsigned* __restrict__ wqkvp,
                                                unsigned* __restrict__ wop,
                                                unsigned* __restrict__ w01p,
                                                unsigned* __restrict__ w2p)
{
    int bid = blockIdx.x;
    if (bid < QKV_BLKS) {
        int p = bid * 256 + threadIdx.x;
        if (p >= QKV_WORDS) return;
        const int perL = DMODEL * QKVW / 2;
        int l = p / perL, dw = p - l * perL;
        int k, n; pack_coords16(dw, QKVW, k, n);
        float v0, v1;
        if (n < 768) {
            const float* s = Wq + ((size_t)l * DMODEL + k) * 768 + n;
            v0 = s[0]; v1 = s[768];
        } else if (n < 1024) {
            const float* s = Wk + ((size_t)l * DMODEL + k) * 256 + (n - 768);
            v0 = s[0]; v1 = s[256];
        } else {
            const float* s = Wv + ((size_t)l * DMODEL + k) * 256 + (n - 1024);
            v0 = s[0]; v1 = s[256];
        }
        wqkvp[(size_t)l * perL + dw] = pack_bf16(v0, v1);
    } else if (bid < QKV_BLKS + WO_BLKS) {
        int p = (bid - QKV_BLKS) * 256 + threadIdx.x;
        if (p >= WO_WORDS) return;
        const int perL = DMODEL * DMODEL / 2;
        int l = p / perL, dw = p - l * perL;
        int k, n; pack_coords16(dw, DMODEL, k, n);
        const float* s = Wo + ((size_t)l * DMODEL + k) * DMODEL + n;
        wop[(size_t)l * perL + dw] = pack_bf16(s[0], s[DMODEL]);
    } else if (bid < QKV_BLKS + WO_BLKS + W01_BLKS) {
        int p = (bid - QKV_BLKS - WO_BLKS) * 256 + threadIdx.x;
        if (p >= W01_WORDS) return;
        const int perL = DMODEL * 2 * FFDIM / 2;
        int l = p / perL, dw = p - l * perL;
        int k, n; pack_coords16(dw, 2 * FFDIM, k, n);
        int f = n >> 1;
        const float* s = ((n & 1) ? w1 : w0) + ((size_t)l * DMODEL + k) * FFDIM + f;
        w01p[(size_t)l * perL + dw] = pack_f16(s[0], s[FFDIM]);
    } else {
        int p = (bid - QKV_BLKS - WO_BLKS - W01_BLKS) * 256 + threadIdx.x;
        if (p >= W2_WORDS) return;
        const int perL = FFDIM * DMODEL / 2;
        int l = p / perL, dw = p - l * perL;
        int k, n; pack_coords16(dw, DMODEL, k, n);
        const float* s = w2 + ((size_t)l * FFDIM + k) * DMODEL + n;
        w2p[(size_t)l * perL + dw] = pack_f16(s[0], s[DMODEL]);
    }
}

// ---------------------------------------------------------------------------
// RMSNorm: PERM 0 = fp32 row-major, 1 = fp16 A-perm, 2 = bf16 A-perm
// ---------------------------------------------------------------------------
template<int PERM>
__global__ void __launch_bounds__(256) rmsnorm_k(const float* __restrict__ x,
                                                 const float* __restrict__ w,
                                                 void* __restrict__ yv)
{
    int row = blockIdx.x;
    const float* xr = x + (size_t)row * DMODEL;
    int t = threadIdx.x;
    float v0 = xr[t], v1 = xr[t + 256], v2 = xr[t + 512];
    float ss = v0*v0 + v1*v1 + v2*v2;
    #pragma unroll
    for (int off = 16; off > 0; off >>= 1)
        ss += __shfl_xor_sync(0xffffffffu, ss, off);
    __shared__ float red[8];
    if ((t & 31) == 0) red[t >> 5] = ss;
    __syncthreads();
    if (t < 32) {
        float s = (t < 8) ? red[t] : 0.f;
        #pragma unroll
        for (int off = 4; off > 0; off >>= 1)
            s += __shfl_xor_sync(0xffffffffu, s, off);
        if (t == 0) red[0] = s;
    }
    __syncthreads();
    float inv = 1.0f / sqrtf(red[0] * (1.0f / DMODEL) + 1e-6f);
    float o0 = v0 * inv * w[t];
    float o1 = v1 * inv * w[t + 256];
    float o2 = v2 * inv * w[t + 512];
    if (PERM == 1) {
        __half* y = (__half*)yv;
        y[aperm_off16(row, t)]       = __float2half_rn(o0);
        y[aperm_off16(row, t + 256)] = __float2half_rn(o1);
        y[aperm_off16(row, t + 512)] = __float2half_rn(o2);
    } else if (PERM == 2) {
        __nv_bfloat16* y = (__nv_bfloat16*)yv;
        y[aperm_off16(row, t)]       = __float2bfloat16(o0);
        y[aperm_off16(row, t + 256)] = __float2bfloat16(o1);
        y[aperm_off16(row, t + 512)] = __float2bfloat16(o2);
    } else {
        float* yr = (float*)yv + (size_t)row * DMODEL;
        yr[t] = o0; yr[t + 256] = o1; yr[t + 512] = o2;
    }
}

// ---------------------------------------------------------------------------
// RoPE on packed qkv (row-major fp32)
// ---------------------------------------------------------------------------
__global__ void __launch_bounds__(256) rope_packed(float* __restrict__ qkv)
{
    int idx = blockIdx.x * 256 + threadIdx.x;
    const int total = ROWS * 16 * 32;
    if (idx >= total) return;
    int i    = idx & 31;
    int hh   = (idx >> 5) & 15;
    int row  = idx >> 9;
    int s    = row & (SEQ - 1);
    float freq = (float)exp(-9.210340371976184 * ((double)i / 32.0));
    float ang = (float)s * freq;
    float sn, cs;
    sincosf(ang, &sn, &cs);
    int coff = (hh < 12) ? hh * 64 : 768 + (hh - 12) * 64;
    float* p = qkv + (size_t)row * QKVW + coff + 2 * i;
    float t0 = p[0], t1 = p[1];
    p[0] = t0 * cs - t1 * sn;
    p[1] = t0 * sn + t1 * cs;
}

// ---------------------------------------------------------------------------
// 16-bit tensor-core GEMM, 128x128 tile, 3-stage cp.async pipeline (R13,
// verified at 943us). K-tile = 64. Stage = 32KB; 96KB dynamic; 2 CTAs/SM.
// MODE 0: C = AB fp32; MODE 1: C = AB + R fp32; MODE 2: silu-gate -> fp16
// A-perm out (K'=N/2).
// ---------------------------------------------------------------------------
template<int MODE, bool FP16>
__global__ void __launch_bounds__(256, 2) tgemm16_k(const void* __restrict__ Ap_,
                                                    const unsigned* __restrict__ Bp,
                                                    void* __restrict__ C_,
                                                    const float* __restrict__ R,
                                                    int N, int K)
{
    extern __shared__ unsigned sm16[];  // 3 x 8192 words; stage: A[0,4096) B[4096,8192)

    int tid = threadIdx.x, lane = tid & 31, warp = tid >> 5;
    int wm = warp >> 2, wn = warp & 3;
    int m0 = blockIdx.y * 128, n0 = blockIdx.x * 128;

    float acc[4][4][4];
    #pragma unroll
    for (int a = 0; a < 4; a++)
        #pragma unroll
        for (int b = 0; b < 4; b++)
            #pragma unroll
            for (int c = 0; c < 4; c++) acc[a][b][c] = 0.f;

    const int n8cnt = N >> 3;
    const uint4* Ag = (const uint4*)Ap_ + (size_t)((m0 >> 4) + warp) * 32 + lane;
    const uint4* Bg = (const uint4*)Bp + (size_t)((n0 >> 3) + (tid >> 4)) * 16 + (tid & 15);

    uint32_t smBase = smem_u32(sm16);
    uint32_t aDst = smBase + (warp * 32 + lane) * 16;
    uint32_t bDst = smBase + 16384 + ((tid >> 4) * 16 + (tid & 15)) * 16;

    const int ntiles = K >> 6;

    #pragma unroll
    for (int t = 0; t < 2; t++) {
        uint32_t sb = t * 32768;
        #pragma unroll
        for (int p = 0; p < 4; p++) {
            int q = 4 * t + p;
            cp16(aDst + sb + p * 4096, Ag + (size_t)q * 8192);
            cp16(bDst + sb + p * 4096, Bg + (size_t)q * n8cnt * 16);
        }
        cp_commit();
    }

    for (int kt = 0; kt < ntiles; kt++) {
        cp_wait1();
        __syncthreads();
        const unsigned* S = sm16 + (kt % 3) * 8192;

        #pragma unroll
        for (int ks = 0; ks < 4; ks++) {
            unsigned af[4][4], bf[4][2];
            #pragma unroll
            for (int mt = 0; mt < 4; mt++)
                *(uint4*)af[mt] = *(const uint4*)&S[ks * 1024 + (wm * 4 + mt) * 128 + lane * 4];
            #pragma unroll
            for (int nt = 0; nt < 4; nt++)
                *(uint2*)bf[nt] = *(const uint2*)&S[4096 + ks * 1024 + (wn * 4 + nt) * 64 + lane * 2];
            #pragma unroll
            for (int mt = 0; mt < 4; mt++)
                #pragma unroll
                for (int nt = 0; nt < 4; nt++)
                    mma16<FP16>(acc[mt][nt], af[mt], bf[nt]);
        }

        int kn = kt + 2;
        if (kn < ntiles) {
            uint32_t sb = (kn % 3) * 32768;
            #pragma unroll
            for (int p = 0; p < 4; p++) {
                int q = 4 * kn + p;
                cp16(aDst + sb + p * 4096, Ag + (size_t)q * 8192);
                cp16(bDst + sb + p * 4096, Bg + (size_t)q * n8cnt * 16);
            }
        }
        cp_commit();
    }

    int g = lane >> 2, tg = lane & 3;
    #pragma unroll
    for (int mt = 0; mt < 4; mt++) {
        int row = m0 + wm * 64 + mt * 16 + g;
        #pragma unroll
        for (int nt = 0; nt < 4; nt++) {
            float* c = acc[mt][nt];
            if (MODE == 2) {
                int f = (n0 >> 1) + wn * 16 + nt * 4 + tg;
                float s0 = c[0] / (1.0f + __expf(-c[0]));
                float s2 = c[2] / (1.0f + __expf(-c[2]));
                __half* Cb = (__half*)C_;
                Cb[aperm_off16(row,     f)] = __float2half_rn(s0 * c[1]);
                Cb[aperm_off16(row + 8, f)] = __float2half_rn(s2 * c[3]);
            } else {
                float* C = (float*)C_;
                int col = n0 + wn * 32 + nt * 8 + tg * 2;
                size_t i0 = (size_t)row * N + col;
                size_t i1 = i0 + (size_t)8 * N;
                float2 v0 = make_float2(c[0], c[1]);
                float2 v1 = make_float2(c[2], c[3]);
                if (MODE == 1) {
                    v0.x += R[i0]; v0.y += R[i0 + 1];
                    v1.x += R[i1]; v1.y += R[i1 + 1];
                }
                *(float2*)&C[i0] = v0;
                *(float2*)&C[i1] = v1;
            }
        }
    }
}

// ---------------------------------------------------------------------------
// bf16 tensor-core flash attention, BQ=128, BK=32. 256 threads = 8 warps;
// warp w owns q-rows [q0+w*16, q0+w*16+16) for ALL keys. 32KB static smem.
// Inner structure identical to the verified R13 kernel; only the m16 (warp)
// dimension widened 4 -> 8. Output bf16 A-perm.
// ---------------------------------------------------------------------------
__global__ void __launch_bounds__(256) flash_kernel(const float* __restrict__ qkv,
                                                    __nv_bfloat16* __restrict__ op)
{
    __shared__ unsigned Qs[4][8][32][4];   // [d16][m16][lane][j]   16KB
    __shared__ unsigned Ks[4][4][32][2];   // [d16][key8][lane][j]   4KB
    __shared__ unsigned Vs[2][8][32][2];   // [key16][dim8][lane][j] 4KB
    __shared__ unsigned Ps[2][8][32][4];   // [key16][m16][lane][j]  8KB

    int qt = blockIdx.x, h = blockIdx.y, b = blockIdx.z;
    int kvh = h / NREP;
    int tid = threadIdx.x, lane = tid & 31, warp = tid >> 5;
    int g = lane >> 2, tg = lane & 3;
    int q0 = qt * 128;

    const float* qbase = qkv + (size_t)(b * SEQ + q0) * QKVW + h * HEADD;
    for (int w = tid; w < 4096; w += 256) {
        int j = w & 3, ln = (w >> 2) & 31, m16 = (w >> 7) & 7, d16 = w >> 10;
        int m = m16 * 16 + (j & 1) * 8 + (ln >> 2);
        int d = d16 * 16 + ((j >> 1) & 1) * 8 + (ln & 3) * 2;
        float2 qv = *(const float2*)(qbase + (size_t)m * QKVW + d);
        Qs[d16][m16][ln][j] = pack_bf16(qv.x, qv.y);
    }

    float mr0 = -INFINITY, mr1 = -INFINITY, l0 = 0.f, l1 = 0.f;
    float o_acc[8][4];
    #pragma unroll
    for (int nt = 0; nt < 8; nt++)
        #pragma unroll
        for (int c = 0; c < 4; c++) o_acc[nt][c] = 0.f;

    const float* kbase = qkv + (size_t)(b * SEQ) * QKVW + 768 + kvh * HEADD;
    const float* vbase = qkv + (size_t)(b * SEQ) * QKVW + 1024 + kvh * HEADD;

    int ntiles = 4 * qt + 4;
    for (int kt = 0; kt < ntiles; kt++) {
        __syncthreads();
        for (int w = tid; w < 1024; w += 256) {
            int j = w & 1, ln = (w >> 1) & 31;
            {
                int key8 = (w >> 6) & 3, d16 = w >> 8;
                int key = key8 * 8 + (ln >> 2);
                int d = d16 * 16 + j * 8 + (ln & 3) * 2;
                float2 kv = *(const float2*)(kbase + (size_t)(kt * 32 + key) * QKVW + d);
                Ks[d16][key8][ln][j] = pack_bf16(kv.x, kv.y);
            }
            {
                int d8 = (w >> 6) & 7, k16 = w >> 9;
                int dim = d8 * 8 + (ln >> 2);
                int key = k16 * 16 + j * 8 + (ln & 3) * 2;
                float v0 = vbase[(size_t)(kt * 32 + key) * QKVW + dim];
                float v1 = vbase[(size_t)(kt * 32 + key + 1) * QKVW + dim];
                Vs[k16][d8][ln][j] = pack_bf16(v0, v1);
            }
        }
        __syncthreads();

        float s[4][4];
        #pragma unroll
        for (int nt = 0; nt < 4; nt++)
            #pragma unroll
            for (int c = 0; c < 4; c++) s[nt][c] = 0.f;

        #pragma unroll
        for (int ks = 0; ks < 4; ks++) {
            unsigned af[4];
            *(uint4*)af = *(const uint4*)&Qs[ks][warp][lane][0];
            #pragma unroll
            for (int nt = 0; nt < 4; nt++) {
                unsigned bf[2];
                *(uint2*)bf = *(const uint2*)&Ks[ks][nt][lane][0];
                mma16<false>(s[nt], af, bf);
            }
        }
        #pragma unroll
        for (int nt = 0; nt < 4; nt++)
            #pragma unroll
            for (int c = 0; c < 4; c++) s[nt][c] *= 0.125f;

        if (kt >= 4 * qt) {
            int qg0 = q0 + warp * 16 + g;
            int qg1 = qg0 + 8;
            #pragma unroll
            for (int nt = 0; nt < 4; nt++) {
                int kg = kt * 32 + nt * 8 + tg * 2;
                if (kg > qg0)     s[nt][0] = -INFINITY;
                if (kg + 1 > qg0) s[nt][1] = -INFINITY;
                if (kg > qg1)     s[nt][2] = -INFINITY;
                if (kg + 1 > qg1) s[nt][3] = -INFINITY;
            }
        }

        float mx0 = -INFINITY, mx1 = -INFINITY;
        #pragma unroll
        for (int nt = 0; nt < 4; nt++) {
            mx0 = fmaxf(mx0, fmaxf(s[nt][0], s[nt][1]));
            mx1 = fmaxf(mx1, fmaxf(s[nt][2], s[nt][3]));
        }
        mx0 = fmaxf(mx0, __shfl_xor_sync(0xffffffffu, mx0, 1));
        mx0 = fmaxf(mx0, __shfl_xor_sync(0xffffffffu, mx0, 2));
        mx1 = fmaxf(mx1, __shfl_xor_sync(0xffffffffu, mx1, 1));
        mx1 = fmaxf(mx1, __shfl_xor_sync(0xffffffffu, mx1, 2));
        float mn0 = fmaxf(mr0, mx0), mn1 = fmaxf(mr1, mx1);
        float sum0 = 0.f, sum1 = 0.f;
        #pragma unroll
        for (int nt = 0; nt < 4; nt++) {
            s[nt][0] = __expf(s[nt][0] - mn0);
            s[nt][1] = __expf(s[nt][1] - mn0);
            s[nt][2] = __expf(s[nt][2] - mn1);
            s[nt][3] = __expf(s[nt][3] - mn1);
            sum0 += s[nt][0] + s[nt][1];
            sum1 += s[nt][2] + s[nt][3];
        }
        sum0 += __shfl_xor_sync(0xffffffffu, sum0, 1);
        sum0 += __shfl_xor_sync(0xffffffffu, sum0, 2);
        sum1 += __shfl_xor_sync(0xffffffffu, sum1, 1);
        sum1 += __shfl_xor_sync(0xffffffffu, sum1, 2);
        float a0 = __expf(mr0 - mn0), a1 = __expf(mr1 - mn1);
        l0 = l0 * a0 + sum0;  l1 = l1 * a1 + sum1;
        mr0 = mn0;  mr1 = mn1;
        #pragma unroll
        for (int nt = 0; nt < 8; nt++) {
            o_acc[nt][0] *= a0; o_acc[nt][1] *= a0;
            o_acc[nt][2] *= a1; o_acc[nt][3] *= a1;
        }

        #pragma unroll
        for (int nt = 0; nt < 4; nt++) {
            Ps[nt >> 1][warp][lane][2 * (nt & 1)]     = pack_bf16(s[nt][0], s[nt][1]);
            Ps[nt >> 1][warp][lane][2 * (nt & 1) + 1] = pack_bf16(s[nt][2], s[nt][3]);
        }
        __syncwarp();

        #pragma unroll
        for (int kks = 0; kks < 2; kks++) {
            unsigned af[4];
            *(uint4*)af = *(const uint4*)&Ps[kks][warp][lane][0];
            #pragma unroll
            for (int nt = 0; nt < 8; nt++) {
                unsigned bf[2];
                *(uint2*)bf = *(const uint2*)&Vs[kks][nt][lane][0];
                mma16<false>(o_acc[nt], af, bf);
            }
        }
        __syncwarp();
    }

    float inv0 = 1.0f / l0, inv1 = 1.0f / l1;
    int mrow = b * SEQ + q0 + warp * 16 + g;
    unsigned* opw = (unsigned*)op;
    #pragma unroll
    for (int nt = 0; nt < 8; nt++) {
        int col = h * HEADD + nt * 8 + tg * 2;
        opw[aperm_woff16(mrow,     col)] = pack_bf16(o_acc[nt][0] * inv0, o_acc[nt][1] * inv0);
        opw[aperm_woff16(mrow + 8, col)] = pack_bf16(o_acc[nt][2] * inv1, o_acc[nt][3] * inv1);
    }
}

// ---------------------------------------------------------------------------
// Launch sequence
// ---------------------------------------------------------------------------
extern "C" void kernel_launch(void* const* d_in, const int* in_sizes, int n_in,
                              void* d_out, int out_size)
{
    (void)in_sizes; (void)n_in; (void)out_size;
    const float* x_in = (const float*)d_in[0];
    const float* Wq   = (const float*)d_in[1];
    const float* Wk   = (const float*)d_in[2];
    const float* Wv   = (const float*)d_in[3];
    const float* Wo   = (const float*)d_in[4];
    const float* an_w = (const float*)d_in[5];
    const float* w0   = (const float*)d_in[6];
    const float* w1   = (const float*)d_in[7];
    const float* w2   = (const float*)d_in[8];
    const float* sn_w = (const float*)d_in[9];
    const float* on_w = (const float*)d_in[10];

    __nv_bfloat16 *hp16, *attnp;
    __half *hpf, *ffp;
    float *qkv, *x;
    unsigned *wqkvp, *wop, *w01p, *w2p;
    cudaGetSymbolAddress((void**)&hp16,  g_hp16);
    cudaGetSymbolAddress((void**)&hpf,   g_hpf);
    cudaGetSymbolAddress((void**)&qkv,   g_qkv);
    cudaGetSymbolAddress((void**)&attnp, g_attnp);
    cudaGetSymbolAddress((void**)&x,     g_x);
    cudaGetSymbolAddress((void**)&ffp,   g_ffp);
    cudaGetSymbolAddress((void**)&wqkvp, g_wqkvp);
    cudaGetSymbolAddress((void**)&wop,   g_wop);
    cudaGetSymbolAddress((void**)&w01p,  g_w01p);
    cudaGetSymbolAddress((void**)&w2p,   g_w2p);

    // allow 96KB dynamic smem (idempotent; not a stream op)
    cudaFuncSetAttribute(tgemm16_k<0,false>, cudaFuncAttributeMaxDynamicSharedMemorySize, GEMM_SMEM);
    cudaFuncSetAttribute(tgemm16_k<1,false>, cudaFuncAttributeMaxDynamicSharedMemorySize, GEMM_SMEM);
    cudaFuncSetAttribute(tgemm16_k<1,true>,  cudaFuncAttributeMaxDynamicSharedMemorySize, GEMM_SMEM);
    cudaFuncSetAttribute(tgemm16_k<2,true>,  cudaFuncAttributeMaxDynamicSharedMemorySize, GEMM_SMEM);

    pack_all<<<PACK_BLKS, 256>>>(Wq, Wk, Wv, Wo, w0, w1, w2, wqkvp, wop, w01p, w2p);

    const float* cur = x_in;
    for (int li = 0; li < LAYERS; li++) {
        // attention side (bf16)
        rmsnorm_k<2><<<ROWS, 256>>>(cur, an_w + (size_t)li * DMODEL, hp16);

        tgemm16_k<0,false><<<dim3(QKVW / 128, ROWS / 128), 256, GEMM_SMEM>>>(
            hp16, wqkvp + (size_t)li * DMODEL * QKVW / 2, qkv, nullptr, QKVW, DMODEL);

        rope_packed<<<(ROWS * 16 * 32 + 255) / 256, 256>>>(qkv);

        flash_kernel<<<dim3(SEQ / 128, NHEADS, BATCH), 256>>>(qkv, attnp);

        tgemm16_k<1,false><<<dim3(DMODEL / 128, ROWS / 128), 256, GEMM_SMEM>>>(
            attnp, wop + (size_t)li * DMODEL * DMODEL / 2, x, cur, DMODEL, DMODEL);

        // FFN side (fp16)
        rmsnorm_k<1><<<ROWS, 256>>>(x, sn_w + (size_t)li * DMODEL, hpf);

        tgemm16_k<2,true><<<dim3(2 * FFDIM / 128, ROWS / 128), 256, GEMM_SMEM>>>(
            hpf, w01p + (size_t)li * DMODEL * 2 * FFDIM / 2, ffp, nullptr, 2 * FFDIM, DMODEL);

        tgemm16_k<1,true><<<dim3(DMODEL / 128, ROWS / 128), 256, GEMM_SMEM>>>(
            ffp, w2p + (size_t)li * FFDIM * DMODEL / 2, x, x, DMODEL, FFDIM);
        cur = x;
    }

    rmsnorm_k<0><<<ROWS, 256>>>(x, on_w, (float*)d_out);
}